// round 15
// baseline (speedup 1.0000x reference)
#include <cuda_runtime.h>
#include <cuda_fp16.h>
#include <cstdint>

#define BATCH 4
#define SEQ 2048
#define DMODEL 1024
#define NHEAD 16
#define HDIM 64
#define MROWS (BATCH*SEQ)

// ---------------- scratch (all half) ----------------
__device__ __half g_xh[(size_t)MROWS*DMODEL];
__device__ __half g_wq[(size_t)DMODEL*DMODEL];
__device__ __half g_wk[(size_t)DMODEL*DMODEL];
__device__ __half g_wv[(size_t)DMODEL*DMODEL];
__device__ __half g_wo[(size_t)DMODEL*DMODEL];
__device__ __half g_q[(size_t)BATCH*NHEAD*SEQ*HDIM];   // [B,H,S,hd]
__device__ __half g_k[(size_t)BATCH*NHEAD*SEQ*HDIM];
__device__ __half g_v[(size_t)BATCH*NHEAD*SEQ*HDIM];
__device__ __half g_attn[(size_t)MROWS*DMODEL];        // [B,S,D]

// ---------------- helpers ----------------
__device__ __forceinline__ uint32_t s2u(const void* p) {
    return (uint32_t)__cvta_generic_to_shared(p);
}
__device__ __forceinline__ void cpa16(uint32_t dst, const void* src) {
    asm volatile("cp.async.cg.shared.global [%0], [%1], 16;" :: "r"(dst), "l"(src));
}
#define CP_COMMIT() asm volatile("cp.async.commit_group;")
#define CP_WAIT(n)  asm volatile("cp.async.wait_group %0;" :: "n"(n))

__device__ __forceinline__ void ldm4(uint32_t (&r)[4], uint32_t a) {
    asm volatile("ldmatrix.sync.aligned.m8n8.x4.shared.b16 {%0,%1,%2,%3}, [%4];"
        : "=r"(r[0]), "=r"(r[1]), "=r"(r[2]), "=r"(r[3]) : "r"(a));
}
__device__ __forceinline__ void ldm4t(uint32_t (&r)[4], uint32_t a) {
    asm volatile("ldmatrix.sync.aligned.m8n8.x4.trans.shared.b16 {%0,%1,%2,%3}, [%4];"
        : "=r"(r[0]), "=r"(r[1]), "=r"(r[2]), "=r"(r[3]) : "r"(a));
}
__device__ __forceinline__ uint32_t h2pack(float lo, float hi) {
    __half2 h = __float22half2_rn(make_float2(lo, hi));
    return *reinterpret_cast<uint32_t*>(&h);
}
// pack two f32 to f16x2 (lo in low half) then exp2 in half2
__device__ __forceinline__ uint32_t ex2h2(float lo, float hi) {
    uint32_t t, r;
    asm("cvt.rn.f16x2.f32 %0, %1, %2;" : "=r"(t) : "f"(hi), "f"(lo));
    asm("ex2.approx.f16x2 %0, %1;" : "=r"(r) : "r"(t));
    return r;
}
__device__ __forceinline__ void mma16(float (&c)[4],
                                      uint32_t a0, uint32_t a1, uint32_t a2, uint32_t a3,
                                      uint32_t b0, uint32_t b1) {
    asm volatile(
        "mma.sync.aligned.m16n8k16.row.col.f32.f16.f16.f32 "
        "{%0,%1,%2,%3}, {%4,%5,%6,%7}, {%8,%9}, {%0,%1,%2,%3};"
        : "+f"(c[0]), "+f"(c[1]), "+f"(c[2]), "+f"(c[3])
        : "r"(a0), "r"(a1), "r"(a2), "r"(a3), "r"(b0), "r"(b1));
}

// ---------------- fused f32 -> f16 convert (all 5 tensors, 1 launch) ------
struct F2HArgs {
    const float* src[5];
    __half*      dst[5];
    int          blkend[5];   // cumulative block ends
};

__global__ __launch_bounds__(256)
void f2h_all(F2HArgs a)
{
    int b = blockIdx.x;
    int seg = 0;
#pragma unroll
    for (int s = 0; s < 4; s++) if (b >= a.blkend[s]) seg = s + 1;
    const int base = seg ? a.blkend[seg - 1] : 0;
    const int i = ((b - base) * 256 + threadIdx.x) * 8;
    const float* in = a.src[seg];
    __half* out = a.dst[seg];
    float4 x = *reinterpret_cast<const float4*>(in + i);
    float4 y = *reinterpret_cast<const float4*>(in + i + 4);
    uint4 o;
    o.x = h2pack(x.x, x.y); o.y = h2pack(x.z, x.w);
    o.z = h2pack(y.x, y.y); o.w = h2pack(y.z, y.w);
    *reinterpret_cast<uint4*>(out + i) = o;
}

// =====================================================================
// GEMM (persistent): C[m,n] = (sum_k A[m,k]*W[n,k] + bias[n]) * scale
// 128x128 tile, 8 warps (2Mx4N), k-chunk 64, cp.async double buffer.
// item -> n-tile (0..7), m-tile (0..63), z (QKV select in MODE 1).
// MODE 1: half output scattered to [B,H,S,hd].  MODE 0: fp32 row-major.
// =====================================================================
#define GSTR 72                 // halves per row (64 + 8 pad); 144 B
#define GSTAGE (128 * GSTR)     // halves per stage per matrix
#define GEMM_SMEM (4 * GSTAGE * 2)   // 2 stages x 2 matrices

struct GemmArgs {
    const __half* W[3];
    const float*  bias[3];
    void*         out[3];
    float         scale[3];
};

template<int MODE>
__global__ __launch_bounds__(256, 2)
void gemm_h(const __half* __restrict__ A, GemmArgs args, int nItems)
{
    extern __shared__ __half smg[];
    __half* sA = smg;                  // [2][GSTAGE]
    __half* sW = smg + 2 * GSTAGE;

    const int tid = threadIdx.x;
    const int lane = tid & 31, warp = tid >> 5;
    const int g = lane >> 2, tc = lane & 3;
    const int wm = (warp >> 2) * 64;
    const int wn = (warp & 3) * 32;

    const uint32_t sAb = s2u(sA), sWb = s2u(sW);

    const uint32_t aoff = (uint32_t)((lane & 15) * GSTR + (lane >> 4) * 8) * 2;
    const uint32_t boff = (uint32_t)(((lane & 7) + ((lane >> 4) << 3)) * GSTR
                                     + ((lane >> 3) & 1) * 8) * 2;

    for (int item = blockIdx.x; item < nItems; item += gridDim.x) {
        const int n0 = (item & 7) * 128;
        const int m0 = ((item >> 3) & 63) * 128;
        const int z = (MODE == 1) ? (item >> 9) : 0;
        const __half* W = args.W[z];
        const float* bias = args.bias[z];
        const float scale = args.scale[z];

        const __half* Ap = A + (size_t)m0 * DMODEL;
        const __half* Wp = W + (size_t)n0 * DMODEL;

        float acc[4][4][4];
#pragma unroll
        for (int mf = 0; mf < 4; mf++)
#pragma unroll
            for (int nf = 0; nf < 4; nf++)
#pragma unroll
                for (int r = 0; r < 4; r++) acc[mf][nf][r] = 0.f;

        // prologue: chunks 0,1
#pragma unroll
        for (int c = 0; c < 2; c++) {
            const uint32_t da = sAb + c * GSTAGE * 2, dw = sWb + c * GSTAGE * 2;
            const int k0 = c * 64;
#pragma unroll
            for (int i = 0; i < 4; i++) {
                int idx = tid + 256 * i, row = idx >> 3, c8 = (idx & 7) * 8;
                cpa16(da + (row * GSTR + c8) * 2, Ap + (size_t)row * DMODEL + k0 + c8);
                cpa16(dw + (row * GSTR + c8) * 2, Wp + (size_t)row * DMODEL + k0 + c8);
            }
            CP_COMMIT();
        }

        for (int c = 0; c < 16; c++) {
            if (c < 15) { CP_WAIT(1); } else { CP_WAIT(0); }
            __syncthreads();
            const int st = c & 1;
            const uint32_t cAb = sAb + st * GSTAGE * 2;
            const uint32_t cWb = sWb + st * GSTAGE * 2;
#pragma unroll
            for (int ks = 0; ks < 4; ks++) {
                const uint32_t kk = ks * 32;
                uint32_t a[4][4];
#pragma unroll
                for (int mf = 0; mf < 4; mf++)
                    ldm4(a[mf], cAb + aoff + (uint32_t)(wm + mf * 16) * (GSTR * 2) + kk);
                uint32_t b[4][2];
#pragma unroll
                for (int nfp = 0; nfp < 2; nfp++) {
                    uint32_t r[4];
                    ldm4(r, cWb + boff + (uint32_t)(wn + nfp * 16) * (GSTR * 2) + kk);
                    b[2 * nfp][0] = r[0]; b[2 * nfp][1] = r[1];
                    b[2 * nfp + 1][0] = r[2]; b[2 * nfp + 1][1] = r[3];
                }
#pragma unroll
                for (int mf = 0; mf < 4; mf++)
#pragma unroll
                    for (int nf = 0; nf < 4; nf++)
                        mma16(acc[mf][nf], a[mf][0], a[mf][1], a[mf][2], a[mf][3],
                              b[nf][0], b[nf][1]);
            }
            __syncthreads();
            if (c + 2 < 16) {
                const uint32_t da = sAb + st * GSTAGE * 2, dw = sWb + st * GSTAGE * 2;
                const int k0 = (c + 2) * 64;
#pragma unroll
                for (int i = 0; i < 4; i++) {
                    int idx = tid + 256 * i, row = idx >> 3, c8 = (idx & 7) * 8;
                    cpa16(da + (row * GSTR + c8) * 2, Ap + (size_t)row * DMODEL + k0 + c8);
                    cpa16(dw + (row * GSTR + c8) * 2, Wp + (size_t)row * DMODEL + k0 + c8);
                }
                CP_COMMIT();
            }
        }

        // epilogue
#pragma unroll
        for (int mf = 0; mf < 4; mf++) {
#pragma unroll
            for (int nf = 0; nf < 4; nf++) {
                const int row = wm + mf * 16 + g;
                const int col = wn + nf * 8 + 2 * tc;
                const float b0 = __ldg(&bias[n0 + col]);
                const float b1 = __ldg(&bias[n0 + col + 1]);
#pragma unroll
                for (int half = 0; half < 2; half++) {
                    const int m = m0 + row + half * 8;
                    const int n = n0 + col;
                    float v0 = (acc[mf][nf][half * 2 + 0] + b0) * scale;
                    float v1 = (acc[mf][nf][half * 2 + 1] + b1) * scale;
                    if (MODE == 0) {
                        *reinterpret_cast<float2*>(
                            (float*)args.out[0] + (size_t)m * DMODEL + n) = make_float2(v0, v1);
                    } else {
                        int bb = m >> 11, s = m & (SEQ - 1);
                        int h = n >> 6, d = n & (HDIM - 1);
                        *reinterpret_cast<uint32_t*>(
                            (__half*)args.out[z] + ((((size_t)bb * NHEAD + h) * SEQ + s) << 6) + d) =
                            h2pack(v0, v1);
                    }
                }
            }
        }
        __syncthreads();   // smem reuse fence before next item's cp.async
    }
}

// =====================================================================
// Attention (persistent): kv macro-tiles of 128 (double-buffered),
// 2x64 sub-tiles, f16x2 exp, row sums via P @ ones mma.
// item -> q-tile (0..15), bh (0..63).
// dyn smem halves: Q[128*72] | K[2][128*72] | V[2][128*72]  = 92160 B
// =====================================================================
#define ASTRH 72
#define AQ_SZ (128 * ASTRH)
#define AT_SZ (128 * ASTRH)
#define ATTN_SMEM ((AQ_SZ + 4 * AT_SZ) * 2)
#define ONE_H2 0x3C003C00u

__global__ __launch_bounds__(256, 2)
void attn_h(const __half* __restrict__ Q, const __half* __restrict__ K,
            const __half* __restrict__ V, __half* __restrict__ Out, int nItems)
{
    extern __shared__ __half sh[];
    const uint32_t Qb = s2u(sh);
    const uint32_t Kb = Qb + AQ_SZ * 2;
    const uint32_t Vb = Kb + 2 * AT_SZ * 2;

    const int tid = threadIdx.x;
    const int lane = tid & 31, warp = tid >> 5;
    const int g = lane >> 2, tc = lane & 3;
    const int wm = warp * 16;

    const uint32_t aoff = (uint32_t)((lane & 15) * ASTRH + (lane >> 4) * 8) * 2;
    const uint32_t koff = (uint32_t)(((lane & 7) + ((lane >> 4) << 3)) * ASTRH
                                     + ((lane >> 3) & 1) * 8) * 2;
    const uint32_t voff = (uint32_t)(((lane & 7) + (((lane >> 3) & 1) << 3)) * ASTRH
                                     + ((lane >> 4) << 3)) * 2;

    for (int item = blockIdx.x; item < nItems; item += gridDim.x) {
        const int q0 = (item & 15) * 128;
        const int bh = item >> 4;

        const __half* Qg = Q + ((size_t)bh * SEQ + q0) * HDIM;
        const __half* Kg = K + (size_t)bh * SEQ * HDIM;
        const __half* Vg = V + (size_t)bh * SEQ * HDIM;

        // prologue: Q (1 group), kv tiles 0 and 1 (1 group each)
#pragma unroll
        for (int i = 0; i < 4; i++) {
            int idx = tid + 256 * i, row = idx >> 3, c8 = (idx & 7) * 8;
            cpa16(Qb + (row * ASTRH + c8) * 2, Qg + (size_t)row * HDIM + c8);
        }
        CP_COMMIT();
#pragma unroll
        for (int t = 0; t < 2; t++) {
            const __half* Kp = Kg + (size_t)t * 128 * HDIM;
            const __half* Vp = Vg + (size_t)t * 128 * HDIM;
            const uint32_t dk = Kb + t * AT_SZ * 2, dv = Vb + t * AT_SZ * 2;
#pragma unroll
            for (int i = 0; i < 4; i++) {
                int idx = tid + 256 * i, row = idx >> 3, c8 = (idx & 7) * 8;
                cpa16(dk + (row * ASTRH + c8) * 2, Kp + (size_t)row * HDIM + c8);
                cpa16(dv + (row * ASTRH + c8) * 2, Vp + (size_t)row * HDIM + c8);
            }
            CP_COMMIT();
        }

        CP_WAIT(2);
        __syncthreads();

        // preload Q fragments (persist across kv tiles of this item)
        uint32_t qa[4][4];
#pragma unroll
        for (int ks = 0; ks < 4; ks++)
            ldm4(qa[ks], Qb + aoff + (uint32_t)wm * (ASTRH * 2) + ks * 32);

        float o[8][4], osum[4];
#pragma unroll
        for (int nf = 0; nf < 8; nf++)
#pragma unroll
            for (int r = 0; r < 4; r++) o[nf][r] = 0.f;
#pragma unroll
        for (int r = 0; r < 4; r++) osum[r] = 0.f;

        for (int it = 0; it < 16; it++) {
            if (it < 15) { CP_WAIT(1); } else { CP_WAIT(0); }
            __syncthreads();
            const int st = it & 1;
            const uint32_t cK = Kb + st * AT_SZ * 2;
            const uint32_t cV = Vb + st * AT_SZ * 2;

#pragma unroll
            for (int sub = 0; sub < 2; sub++) {
                const uint32_t sof = (uint32_t)(sub * 64 * ASTRH * 2);

                // S = Q @ K^T (64 kv cols)
                float s[8][4];
#pragma unroll
                for (int nf = 0; nf < 8; nf++)
#pragma unroll
                    for (int r = 0; r < 4; r++) s[nf][r] = 0.f;
#pragma unroll
                for (int ks = 0; ks < 4; ks++) {
                    uint32_t b[8][2];
#pragma unroll
                    for (int nfp = 0; nfp < 4; nfp++) {
                        uint32_t r[4];
                        ldm4(r, cK + sof + koff + (uint32_t)(nfp * 16) * (ASTRH * 2) + ks * 32);
                        b[2 * nfp][0] = r[0]; b[2 * nfp][1] = r[1];
                        b[2 * nfp + 1][0] = r[2]; b[2 * nfp + 1][1] = r[3];
                    }
#pragma unroll
                    for (int nf = 0; nf < 8; nf++)
                        mma16(s[nf], qa[ks][0], qa[ks][1], qa[ks][2], qa[ks][3],
                              b[nf][0], b[nf][1]);
                }

                // P = exp2(S) in half2
                uint32_t ph[8][2];
#pragma unroll
                for (int nf = 0; nf < 8; nf++) {
                    ph[nf][0] = ex2h2(s[nf][0], s[nf][1]);
                    ph[nf][1] = ex2h2(s[nf][2], s[nf][3]);
                }

                // O += P @ V ; row sums += P @ ones
#pragma unroll
                for (int ks = 0; ks < 4; ks++) {
                    uint32_t b[8][2];
#pragma unroll
                    for (int nfp = 0; nfp < 4; nfp++) {
                        uint32_t r[4];
                        ldm4t(r, cV + sof + voff + (uint32_t)(ks * 16) * (ASTRH * 2) + nfp * 32);
                        b[2 * nfp][0] = r[0]; b[2 * nfp][1] = r[1];
                        b[2 * nfp + 1][0] = r[2]; b[2 * nfp + 1][1] = r[3];
                    }
#pragma unroll
                    for (int nf = 0; nf < 8; nf++)
                        mma16(o[nf], ph[2 * ks][0], ph[2 * ks][1],
                              ph[2 * ks + 1][0], ph[2 * ks + 1][1],
                              b[nf][0], b[nf][1]);
                    mma16(osum, ph[2 * ks][0], ph[2 * ks][1],
                          ph[2 * ks + 1][0], ph[2 * ks + 1][1], ONE_H2, ONE_H2);
                }
            }
            __syncthreads();
            if (it + 2 < 16) {
                const __half* Kp = Kg + (size_t)(it + 2) * 128 * HDIM;
                const __half* Vp = Vg + (size_t)(it + 2) * 128 * HDIM;
                const uint32_t dk = Kb + st * AT_SZ * 2, dv = Vb + st * AT_SZ * 2;
#pragma unroll
                for (int i = 0; i < 4; i++) {
                    int idx = tid + 256 * i, row = idx >> 3, c8 = (idx & 7) * 8;
                    cpa16(dk + (row * ASTRH + c8) * 2, Kp + (size_t)row * HDIM + c8);
                    cpa16(dv + (row * ASTRH + c8) * 2, Vp + (size_t)row * HDIM + c8);
                }
                CP_COMMIT();
            }
        }

        const float inv0 = 1.f / osum[0], inv1 = 1.f / osum[2];

        // epilogue: half, concat layout [B,S,D]
        const int b = bh >> 4, hh = bh & 15;
        __half* op0 = Out + ((size_t)(b * SEQ + q0 + wm + g)) * DMODEL + hh * HDIM;
        __half* op1 = op0 + (size_t)8 * DMODEL;
#pragma unroll
        for (int nf = 0; nf < 8; nf++) {
            const int col = nf * 8 + 2 * tc;
            *reinterpret_cast<uint32_t*>(op0 + col) = h2pack(o[nf][0] * inv0, o[nf][1] * inv0);
            *reinterpret_cast<uint32_t*>(op1 + col) = h2pack(o[nf][2] * inv1, o[nf][3] * inv1);
        }
        __syncthreads();   // smem reuse fence before next item's cp.async
    }
}

// =====================================================================
extern "C" void kernel_launch(void* const* d_in, const int* in_sizes, int n_in,
                              void* d_out, int out_size)
{
    const float* x   = (const float*)d_in[0];
    const float* w_q = (const float*)d_in[1];
    const float* b_q = (const float*)d_in[2];
    const float* w_k = (const float*)d_in[3];
    const float* b_k = (const float*)d_in[4];
    const float* w_v = (const float*)d_in[5];
    const float* b_v = (const float*)d_in[6];
    const float* w_o = (const float*)d_in[7];
    const float* b_o = (const float*)d_in[8];
    float* out = (float*)d_out;

    __half *xh, *wq, *wk, *wv, *wo, *pq, *pk, *pv, *pattn;
    cudaGetSymbolAddress((void**)&xh, g_xh);
    cudaGetSymbolAddress((void**)&wq, g_wq);
    cudaGetSymbolAddress((void**)&wk, g_wk);
    cudaGetSymbolAddress((void**)&wv, g_wv);
    cudaGetSymbolAddress((void**)&wo, g_wo);
    cudaGetSymbolAddress((void**)&pq, g_q);
    cudaGetSymbolAddress((void**)&pk, g_k);
    cudaGetSymbolAddress((void**)&pv, g_v);
    cudaGetSymbolAddress((void**)&pattn, g_attn);

    static int nsm = 0;
    if (!nsm) {
        int dev = 0;
        cudaGetDevice(&dev);
        cudaDeviceGetAttribute(&nsm, cudaDevAttrMultiProcessorCount, dev);
        cudaFuncSetAttribute(gemm_h<0>, cudaFuncAttributeMaxDynamicSharedMemorySize, GEMM_SMEM);
        cudaFuncSetAttribute(gemm_h<1>, cudaFuncAttributeMaxDynamicSharedMemorySize, GEMM_SMEM);
        cudaFuncSetAttribute(attn_h,    cudaFuncAttributeMaxDynamicSharedMemorySize, ATTN_SMEM);
    }
    const int pgrid = 2 * nsm;   // 2 CTAs resident per SM

    // fused converts: x (4096 blocks) + 4 weights (512 each)
    const int NXB = (MROWS * DMODEL) / 2048, NWB = (DMODEL * DMODEL) / 2048;
    F2HArgs fa;
    fa.src[0] = x;   fa.dst[0] = xh;  fa.blkend[0] = NXB;
    fa.src[1] = w_q; fa.dst[1] = wq;  fa.blkend[1] = NXB + NWB;
    fa.src[2] = w_k; fa.dst[2] = wk;  fa.blkend[2] = NXB + 2 * NWB;
    fa.src[3] = w_v; fa.dst[3] = wv;  fa.blkend[3] = NXB + 3 * NWB;
    fa.src[4] = w_o; fa.dst[4] = wo;  fa.blkend[4] = NXB + 4 * NWB;
    f2h_all<<<NXB + 4 * NWB, 256>>>(fa);

    const float qscale = 0.18033688011112042f;   // (1/8) * log2(e)

    GemmArgs qkv;
    qkv.W[0] = wq;  qkv.W[1] = wk;  qkv.W[2] = wv;
    qkv.bias[0] = b_q; qkv.bias[1] = b_k; qkv.bias[2] = b_v;
    qkv.out[0] = pq; qkv.out[1] = pk; qkv.out[2] = pv;
    qkv.scale[0] = qscale; qkv.scale[1] = 1.0f; qkv.scale[2] = 1.0f;

    gemm_h<1><<<pgrid, 256, GEMM_SMEM>>>(xh, qkv, 3 * 512);   // 1536 tiles

    attn_h<<<pgrid, 256, ATTN_SMEM>>>(pq, pk, pv, pattn, 1024);

    GemmArgs og;
    og.W[0] = wo; og.W[1] = wo; og.W[2] = wo;
    og.bias[0] = b_o; og.bias[1] = b_o; og.bias[2] = b_o;
    og.out[0] = out; og.out[1] = out; og.out[2] = out;
    og.scale[0] = 1.0f; og.scale[1] = 1.0f; og.scale[2] = 1.0f;

    gemm_h<0><<<pgrid, 256, GEMM_SMEM>>>(pattn, og, 512);
}

// round 17
// speedup vs baseline: 1.0105x; 1.0105x over previous
#include <cuda_runtime.h>
#include <cuda_fp16.h>
#include <cstdint>

#define BATCH 4
#define SEQ 2048
#define DMODEL 1024
#define NHEAD 16
#define HDIM 64
#define MROWS (BATCH*SEQ)

// ---------------- scratch (all half) ----------------
__device__ __half g_xh[(size_t)MROWS*DMODEL];
__device__ __half g_wq[(size_t)DMODEL*DMODEL];
__device__ __half g_wk[(size_t)DMODEL*DMODEL];
__device__ __half g_wv[(size_t)DMODEL*DMODEL];
__device__ __half g_wo[(size_t)DMODEL*DMODEL];
__device__ __half g_q[(size_t)BATCH*NHEAD*SEQ*HDIM];   // [B,H,S,hd]
__device__ __half g_k[(size_t)BATCH*NHEAD*SEQ*HDIM];
__device__ __half g_v[(size_t)BATCH*NHEAD*SEQ*HDIM];
__device__ __half g_attn[(size_t)MROWS*DMODEL];        // [B,S,D]

// ---------------- helpers ----------------
__device__ __forceinline__ uint32_t s2u(const void* p) {
    return (uint32_t)__cvta_generic_to_shared(p);
}
__device__ __forceinline__ void cpa16(uint32_t dst, const void* src) {
    asm volatile("cp.async.cg.shared.global [%0], [%1], 16;" :: "r"(dst), "l"(src));
}
#define CP_COMMIT() asm volatile("cp.async.commit_group;")
#define CP_WAIT(n)  asm volatile("cp.async.wait_group %0;" :: "n"(n))

__device__ __forceinline__ void ldm4(uint32_t (&r)[4], uint32_t a) {
    asm volatile("ldmatrix.sync.aligned.m8n8.x4.shared.b16 {%0,%1,%2,%3}, [%4];"
        : "=r"(r[0]), "=r"(r[1]), "=r"(r[2]), "=r"(r[3]) : "r"(a));
}
__device__ __forceinline__ void ldm4t(uint32_t (&r)[4], uint32_t a) {
    asm volatile("ldmatrix.sync.aligned.m8n8.x4.trans.shared.b16 {%0,%1,%2,%3}, [%4];"
        : "=r"(r[0]), "=r"(r[1]), "=r"(r[2]), "=r"(r[3]) : "r"(a));
}
__device__ __forceinline__ uint32_t h2pack(float lo, float hi) {
    __half2 h = __float22half2_rn(make_float2(lo, hi));
    return *reinterpret_cast<uint32_t*>(&h);
}
// pack two f32 to f16x2 (lo in low half) then exp2 in half2
__device__ __forceinline__ uint32_t ex2h2(float lo, float hi) {
    uint32_t t, r;
    asm("cvt.rn.f16x2.f32 %0, %1, %2;" : "=r"(t) : "f"(hi), "f"(lo));
    asm("ex2.approx.f16x2 %0, %1;" : "=r"(r) : "r"(t));
    return r;
}
__device__ __forceinline__ void mma16(float (&c)[4],
                                      uint32_t a0, uint32_t a1, uint32_t a2, uint32_t a3,
                                      uint32_t b0, uint32_t b1) {
    asm volatile(
        "mma.sync.aligned.m16n8k16.row.col.f32.f16.f16.f32 "
        "{%0,%1,%2,%3}, {%4,%5,%6,%7}, {%8,%9}, {%0,%1,%2,%3};"
        : "+f"(c[0]), "+f"(c[1]), "+f"(c[2]), "+f"(c[3])
        : "r"(a0), "r"(a1), "r"(a2), "r"(a3), "r"(b0), "r"(b1));
}

// ---------------- fused f32 -> f16 convert (all 5 tensors, 1 launch) ------
struct F2HArgs {
    const float* src[5];
    __half*      dst[5];
    int          blkend[5];   // cumulative block ends
};

__global__ __launch_bounds__(256)
void f2h_all(F2HArgs a)
{
    int b = blockIdx.x;
    int seg = 0;
#pragma unroll
    for (int s = 0; s < 4; s++) if (b >= a.blkend[s]) seg = s + 1;
    const int base = seg ? a.blkend[seg - 1] : 0;
    const int i = ((b - base) * 256 + threadIdx.x) * 8;
    const float* in = a.src[seg];
    __half* out = a.dst[seg];
    float4 x = *reinterpret_cast<const float4*>(in + i);
    float4 y = *reinterpret_cast<const float4*>(in + i + 4);
    uint4 o;
    o.x = h2pack(x.x, x.y); o.y = h2pack(x.z, x.w);
    o.z = h2pack(y.x, y.y); o.w = h2pack(y.z, y.w);
    *reinterpret_cast<uint4*>(out + i) = o;
}

// =====================================================================
// GEMM: C[m,n] = (sum_k A[m,k]*W[n,k] + bias[n]) * scale
// 128x128 tile, 8 warps (2Mx4N), k-chunk 64, cp.async double buffer.
// MODE 1: grid.z selects QKV; half output scattered to [B,H,S,hd].
// MODE 0: fp32 row-major output.
// =====================================================================
#define GSTR 72                 // halves per row (64 + 8 pad); 144 B
#define GSTAGE (128 * GSTR)     // halves per stage per matrix
#define GEMM_SMEM (4 * GSTAGE * 2)   // 2 stages x 2 matrices

struct GemmArgs {
    const __half* W[3];
    const float*  bias[3];
    void*         out[3];
    float         scale[3];
};

template<int MODE>
__global__ __launch_bounds__(256, 2)
void gemm_h(const __half* __restrict__ A, GemmArgs args)
{
    extern __shared__ __half smg[];
    __half* sA = smg;                  // [2][GSTAGE]
    __half* sW = smg + 2 * GSTAGE;

    const int z = (MODE == 1) ? blockIdx.z : 0;
    const __half* W = args.W[z];
    const float* bias = args.bias[z];
    const float scale = args.scale[z];

    const int tid = threadIdx.x;
    const int lane = tid & 31, warp = tid >> 5;
    const int g = lane >> 2, tc = lane & 3;
    const int wm = (warp >> 2) * 64;
    const int wn = (warp & 3) * 32;
    const int m0 = blockIdx.y * 128, n0 = blockIdx.x * 128;

    const uint32_t sAb = s2u(sA), sWb = s2u(sW);

    const __half* Ap = A + (size_t)m0 * DMODEL;
    const __half* Wp = W + (size_t)n0 * DMODEL;

    const uint32_t aoff = (uint32_t)((lane & 15) * GSTR + (lane >> 4) * 8) * 2;
    const uint32_t boff = (uint32_t)(((lane & 7) + ((lane >> 4) << 3)) * GSTR
                                     + ((lane >> 3) & 1) * 8) * 2;

    float acc[4][4][4];
#pragma unroll
    for (int mf = 0; mf < 4; mf++)
#pragma unroll
        for (int nf = 0; nf < 4; nf++)
#pragma unroll
            for (int r = 0; r < 4; r++) acc[mf][nf][r] = 0.f;

    // prologue: chunks 0,1
#pragma unroll
    for (int c = 0; c < 2; c++) {
        const uint32_t da = sAb + c * GSTAGE * 2, dw = sWb + c * GSTAGE * 2;
        const int k0 = c * 64;
#pragma unroll
        for (int i = 0; i < 4; i++) {
            int idx = tid + 256 * i, row = idx >> 3, c8 = (idx & 7) * 8;
            cpa16(da + (row * GSTR + c8) * 2, Ap + (size_t)row * DMODEL + k0 + c8);
            cpa16(dw + (row * GSTR + c8) * 2, Wp + (size_t)row * DMODEL + k0 + c8);
        }
        CP_COMMIT();
    }

    for (int c = 0; c < 16; c++) {
        if (c < 15) { CP_WAIT(1); } else { CP_WAIT(0); }
        __syncthreads();
        const int st = c & 1;
        const uint32_t cAb = sAb + st * GSTAGE * 2;
        const uint32_t cWb = sWb + st * GSTAGE * 2;
#pragma unroll
        for (int ks = 0; ks < 4; ks++) {
            const uint32_t kk = ks * 32;
            uint32_t a[4][4];
#pragma unroll
            for (int mf = 0; mf < 4; mf++)
                ldm4(a[mf], cAb + aoff + (uint32_t)(wm + mf * 16) * (GSTR * 2) + kk);
            uint32_t b[4][2];
#pragma unroll
            for (int nfp = 0; nfp < 2; nfp++) {
                uint32_t r[4];
                ldm4(r, cWb + boff + (uint32_t)(wn + nfp * 16) * (GSTR * 2) + kk);
                b[2 * nfp][0] = r[0]; b[2 * nfp][1] = r[1];
                b[2 * nfp + 1][0] = r[2]; b[2 * nfp + 1][1] = r[3];
            }
#pragma unroll
            for (int mf = 0; mf < 4; mf++)
#pragma unroll
                for (int nf = 0; nf < 4; nf++)
                    mma16(acc[mf][nf], a[mf][0], a[mf][1], a[mf][2], a[mf][3],
                          b[nf][0], b[nf][1]);
        }
        __syncthreads();
        if (c + 2 < 16) {
            const uint32_t da = sAb + st * GSTAGE * 2, dw = sWb + st * GSTAGE * 2;
            const int k0 = (c + 2) * 64;
#pragma unroll
            for (int i = 0; i < 4; i++) {
                int idx = tid + 256 * i, row = idx >> 3, c8 = (idx & 7) * 8;
                cpa16(da + (row * GSTR + c8) * 2, Ap + (size_t)row * DMODEL + k0 + c8);
                cpa16(dw + (row * GSTR + c8) * 2, Wp + (size_t)row * DMODEL + k0 + c8);
            }
            CP_COMMIT();
        }
    }

    // epilogue
#pragma unroll
    for (int mf = 0; mf < 4; mf++) {
#pragma unroll
        for (int nf = 0; nf < 4; nf++) {
            const int row = wm + mf * 16 + g;
            const int col = wn + nf * 8 + 2 * tc;
            const float b0 = __ldg(&bias[n0 + col]);
            const float b1 = __ldg(&bias[n0 + col + 1]);
#pragma unroll
            for (int half = 0; half < 2; half++) {
                const int m = m0 + row + half * 8;
                const int n = n0 + col;
                float v0 = (acc[mf][nf][half * 2 + 0] + b0) * scale;
                float v1 = (acc[mf][nf][half * 2 + 1] + b1) * scale;
                if (MODE == 0) {
                    *reinterpret_cast<float2*>(
                        (float*)args.out[0] + (size_t)m * DMODEL + n) = make_float2(v0, v1);
                } else {
                    int bb = m >> 11, s = m & (SEQ - 1);
                    int h = n >> 6, d = n & (HDIM - 1);
                    *reinterpret_cast<uint32_t*>(
                        (__half*)args.out[z] + ((((size_t)bb * NHEAD + h) * SEQ + s) << 6) + d) =
                        h2pack(v0, v1);
                }
            }
        }
    }
}

// =====================================================================
// Attention: kv macro-tiles of 128 (double-buffered), 2x64 sub-tiles.
// f16x2 exp; row sums via P @ ones tensor-core mma (exact f32).
// dyn smem halves: Q[128*72] | K[2][128*72] | V[2][128*72]  = 92160 B
// =====================================================================
#define ASTRH 72
#define AQ_SZ (128 * ASTRH)
#define AT_SZ (128 * ASTRH)
#define ATTN_SMEM ((AQ_SZ + 4 * AT_SZ) * 2)
#define ONE_H2 0x3C003C00u

__global__ __launch_bounds__(256, 2)
void attn_h(const __half* __restrict__ Q, const __half* __restrict__ K,
            const __half* __restrict__ V, __half* __restrict__ Out)
{
    extern __shared__ __half sh[];
    const uint32_t Qb = s2u(sh);
    const uint32_t Kb = Qb + AQ_SZ * 2;
    const uint32_t Vb = Kb + 2 * AT_SZ * 2;

    const int tid = threadIdx.x;
    const int lane = tid & 31, warp = tid >> 5;
    const int g = lane >> 2, tc = lane & 3;
    const int wm = warp * 16;
    const int q0 = blockIdx.x * 128;
    const int bh = blockIdx.y;

    const __half* Qg = Q + ((size_t)bh * SEQ + q0) * HDIM;
    const __half* Kg = K + (size_t)bh * SEQ * HDIM;
    const __half* Vg = V + (size_t)bh * SEQ * HDIM;

    // prologue: Q (1 group), kv tiles 0 and 1 (1 group each)
#pragma unroll
    for (int i = 0; i < 4; i++) {
        int idx = tid + 256 * i, row = idx >> 3, c8 = (idx & 7) * 8;
        cpa16(Qb + (row * ASTRH + c8) * 2, Qg + (size_t)row * HDIM + c8);
    }
    CP_COMMIT();
#pragma unroll
    for (int t = 0; t < 2; t++) {
        const __half* Kp = Kg + (size_t)t * 128 * HDIM;
        const __half* Vp = Vg + (size_t)t * 128 * HDIM;
        const uint32_t dk = Kb + t * AT_SZ * 2, dv = Vb + t * AT_SZ * 2;
#pragma unroll
        for (int i = 0; i < 4; i++) {
            int idx = tid + 256 * i, row = idx >> 3, c8 = (idx & 7) * 8;
            cpa16(dk + (row * ASTRH + c8) * 2, Kp + (size_t)row * HDIM + c8);
            cpa16(dv + (row * ASTRH + c8) * 2, Vp + (size_t)row * HDIM + c8);
        }
        CP_COMMIT();
    }

    CP_WAIT(2);
    __syncthreads();

    const uint32_t aoff = (uint32_t)((lane & 15) * ASTRH + (lane >> 4) * 8) * 2;
    uint32_t qa[4][4];
#pragma unroll
    for (int ks = 0; ks < 4; ks++)
        ldm4(qa[ks], Qb + aoff + (uint32_t)wm * (ASTRH * 2) + ks * 32);

    const uint32_t koff = (uint32_t)(((lane & 7) + ((lane >> 4) << 3)) * ASTRH
                                     + ((lane >> 3) & 1) * 8) * 2;
    const uint32_t voff = (uint32_t)(((lane & 7) + (((lane >> 3) & 1) << 3)) * ASTRH
                                     + ((lane >> 4) << 3)) * 2;

    float o[8][4], osum[4];
#pragma unroll
    for (int nf = 0; nf < 8; nf++)
#pragma unroll
        for (int r = 0; r < 4; r++) o[nf][r] = 0.f;
#pragma unroll
    for (int r = 0; r < 4; r++) osum[r] = 0.f;

    for (int it = 0; it < 16; it++) {
        if (it < 15) { CP_WAIT(1); } else { CP_WAIT(0); }
        __syncthreads();
        const int st = it & 1;
        const uint32_t cK = Kb + st * AT_SZ * 2;
        const uint32_t cV = Vb + st * AT_SZ * 2;

#pragma unroll
        for (int sub = 0; sub < 2; sub++) {
            const uint32_t sof = (uint32_t)(sub * 64 * ASTRH * 2);

            // S = Q @ K^T (64 kv cols)
            float s[8][4];
#pragma unroll
            for (int nf = 0; nf < 8; nf++)
#pragma unroll
                for (int r = 0; r < 4; r++) s[nf][r] = 0.f;
#pragma unroll
            for (int ks = 0; ks < 4; ks++) {
                uint32_t b[8][2];
#pragma unroll
                for (int nfp = 0; nfp < 4; nfp++) {
                    uint32_t r[4];
                    ldm4(r, cK + sof + koff + (uint32_t)(nfp * 16) * (ASTRH * 2) + ks * 32);
                    b[2 * nfp][0] = r[0]; b[2 * nfp][1] = r[1];
                    b[2 * nfp + 1][0] = r[2]; b[2 * nfp + 1][1] = r[3];
                }
#pragma unroll
                for (int nf = 0; nf < 8; nf++)
                    mma16(s[nf], qa[ks][0], qa[ks][1], qa[ks][2], qa[ks][3],
                          b[nf][0], b[nf][1]);
            }

            // P = exp2(S) in half2
            uint32_t ph[8][2];
#pragma unroll
            for (int nf = 0; nf < 8; nf++) {
                ph[nf][0] = ex2h2(s[nf][0], s[nf][1]);
                ph[nf][1] = ex2h2(s[nf][2], s[nf][3]);
            }

            // O += P @ V ; row sums += P @ ones
#pragma unroll
            for (int ks = 0; ks < 4; ks++) {
                uint32_t b[8][2];
#pragma unroll
                for (int nfp = 0; nfp < 4; nfp++) {
                    uint32_t r[4];
                    ldm4t(r, cV + sof + voff + (uint32_t)(ks * 16) * (ASTRH * 2) + nfp * 32);
                    b[2 * nfp][0] = r[0]; b[2 * nfp][1] = r[1];
                    b[2 * nfp + 1][0] = r[2]; b[2 * nfp + 1][1] = r[3];
                }
#pragma unroll
                for (int nf = 0; nf < 8; nf++)
                    mma16(o[nf], ph[2 * ks][0], ph[2 * ks][1],
                          ph[2 * ks + 1][0], ph[2 * ks + 1][1],
                          b[nf][0], b[nf][1]);
                mma16(osum, ph[2 * ks][0], ph[2 * ks][1],
                      ph[2 * ks + 1][0], ph[2 * ks + 1][1], ONE_H2, ONE_H2);
            }
        }
        __syncthreads();
        if (it + 2 < 16) {
            const __half* Kp = Kg + (size_t)(it + 2) * 128 * HDIM;
            const __half* Vp = Vg + (size_t)(it + 2) * 128 * HDIM;
            const uint32_t dk = Kb + st * AT_SZ * 2, dv = Vb + st * AT_SZ * 2;
#pragma unroll
            for (int i = 0; i < 4; i++) {
                int idx = tid + 256 * i, row = idx >> 3, c8 = (idx & 7) * 8;
                cpa16(dk + (row * ASTRH + c8) * 2, Kp + (size_t)row * HDIM + c8);
                cpa16(dv + (row * ASTRH + c8) * 2, Vp + (size_t)row * HDIM + c8);
            }
            CP_COMMIT();
        }
    }

    const float inv0 = 1.f / osum[0], inv1 = 1.f / osum[2];

    // epilogue: half, concat layout [B,S,D]
    const int b = bh >> 4, hh = bh & 15;
    __half* op0 = Out + ((size_t)(b * SEQ + q0 + wm + g)) * DMODEL + hh * HDIM;
    __half* op1 = op0 + (size_t)8 * DMODEL;
#pragma unroll
    for (int nf = 0; nf < 8; nf++) {
        const int col = nf * 8 + 2 * tc;
        *reinterpret_cast<uint32_t*>(op0 + col) = h2pack(o[nf][0] * inv0, o[nf][1] * inv0);
        *reinterpret_cast<uint32_t*>(op1 + col) = h2pack(o[nf][2] * inv1, o[nf][3] * inv1);
    }
}

// =====================================================================
extern "C" void kernel_launch(void* const* d_in, const int* in_sizes, int n_in,
                              void* d_out, int out_size)
{
    const float* x   = (const float*)d_in[0];
    const float* w_q = (const float*)d_in[1];
    const float* b_q = (const float*)d_in[2];
    const float* w_k = (const float*)d_in[3];
    const float* b_k = (const float*)d_in[4];
    const float* w_v = (const float*)d_in[5];
    const float* b_v = (const float*)d_in[6];
    const float* w_o = (const float*)d_in[7];
    const float* b_o = (const float*)d_in[8];
    float* out = (float*)d_out;

    __half *xh, *wq, *wk, *wv, *wo, *pq, *pk, *pv, *pattn;
    cudaGetSymbolAddress((void**)&xh, g_xh);
    cudaGetSymbolAddress((void**)&wq, g_wq);
    cudaGetSymbolAddress((void**)&wk, g_wk);
    cudaGetSymbolAddress((void**)&wv, g_wv);
    cudaGetSymbolAddress((void**)&wo, g_wo);
    cudaGetSymbolAddress((void**)&pq, g_q);
    cudaGetSymbolAddress((void**)&pk, g_k);
    cudaGetSymbolAddress((void**)&pv, g_v);
    cudaGetSymbolAddress((void**)&pattn, g_attn);

    static bool init = false;
    if (!init) {
        cudaFuncSetAttribute(gemm_h<0>, cudaFuncAttributeMaxDynamicSharedMemorySize, GEMM_SMEM);
        cudaFuncSetAttribute(gemm_h<1>, cudaFuncAttributeMaxDynamicSharedMemorySize, GEMM_SMEM);
        cudaFuncSetAttribute(attn_h,    cudaFuncAttributeMaxDynamicSharedMemorySize, ATTN_SMEM);
        init = true;
    }

    // fused converts: x (4096 blocks) + 4 weights (512 each) in ONE launch
    const int NXB = (MROWS * DMODEL) / 2048, NWB = (DMODEL * DMODEL) / 2048;
    F2HArgs fa;
    fa.src[0] = x;   fa.dst[0] = xh;  fa.blkend[0] = NXB;
    fa.src[1] = w_q; fa.dst[1] = wq;  fa.blkend[1] = NXB + NWB;
    fa.src[2] = w_k; fa.dst[2] = wk;  fa.blkend[2] = NXB + 2 * NWB;
    fa.src[3] = w_v; fa.dst[3] = wv;  fa.blkend[3] = NXB + 3 * NWB;
    fa.src[4] = w_o; fa.dst[4] = wo;  fa.blkend[4] = NXB + 4 * NWB;
    f2h_all<<<NXB + 4 * NWB, 256>>>(fa);

    const float qscale = 0.18033688011112042f;   // (1/8) * log2(e)

    GemmArgs qkv;
    qkv.W[0] = wq;  qkv.W[1] = wk;  qkv.W[2] = wv;
    qkv.bias[0] = b_q; qkv.bias[1] = b_k; qkv.bias[2] = b_v;
    qkv.out[0] = pq; qkv.out[1] = pk; qkv.out[2] = pv;
    qkv.scale[0] = qscale; qkv.scale[1] = 1.0f; qkv.scale[2] = 1.0f;

    dim3 gp3(DMODEL / 128, MROWS / 128, 3);      // (8, 64, 3)
    gemm_h<1><<<gp3, 256, GEMM_SMEM>>>(xh, qkv);

    dim3 ga(SEQ / 128, BATCH * NHEAD);           // (16, 64)
    attn_h<<<ga, 256, ATTN_SMEM>>>(pq, pk, pv, pattn);

    GemmArgs og;
    og.W[0] = wo; og.W[1] = wo; og.W[2] = wo;
    og.bias[0] = b_o; og.bias[1] = b_o; og.bias[2] = b_o;
    og.out[0] = out; og.out[1] = out; og.out[2] = out;
    og.scale[0] = 1.0f; og.scale[1] = 1.0f; og.scale[2] = 1.0f;

    dim3 gp(DMODEL / 128, MROWS / 128, 1);
    gemm_h<0><<<gp, 256, GEMM_SMEM>>>(pattn, og);
}